// round 6
// baseline (speedup 1.0000x reference)
#include <cuda_runtime.h>
#include <cstdint>

// StructureTensorEffect, B=4, C=3, H=W=1024.
// Separable form: s_u = Gx*Sy, s_v = Sx*Gy, per-batch-constant stencils.
// sigma in [0.5,2.5) => JP = floor(sigma) in {0,1,2}, JM = -JP-1.
//
// R6: ZERO shared memory. One warp owns a 128-px row segment (lane k owns
// float4 at strip*128+4k). Vertical stencil from 5 clamped-row LDG.128
// (L1-hit heavy), horizontal halo via __shfl_up/down of neighbors' vertical
// results; strip edges via a per-lane aux column. No STS/LDS/barriers.
// Border pixels (outer 3) use an exact 8-tap bilinear fallback.

#define Wd 1024
#define Hd 1024
#define HW (Hd*Wd)
#define NTH 128
#define NW  4              // warps per block
#define ROWS 4             // rows per warp
#define FULLM 0xffffffffu

__device__ __forceinline__ int clampi(int v, int lo, int hi) {
    return min(max(v, lo), hi);
}

// Exact per-pixel path replicating reference clip semantics (border only).
__device__ __noinline__ void exact_pixel(const float* __restrict__ xb, float s,
                                         int gx, int gy,
                                         float& A, float& Bv, float& Cv) {
    const float OU[8] = {-1.f,-1.f,-1.f, 0.f, 0.f, 1.f, 1.f, 1.f};
    const float OV[8] = {-1.f, 0.f, 1.f,-1.f, 1.f,-1.f, 0.f, 1.f};
    const float KU[8] = {-0.25f,-0.5f,-0.25f, 0.f, 0.f, 0.25f, 0.5f, 0.25f};
    const float KV[8] = {-0.25f, 0.f, 0.25f,-0.5f, 0.5f,-0.25f, 0.f, 0.25f};
    float su[3] = {0.f,0.f,0.f}, sv[3] = {0.f,0.f,0.f};
    #pragma unroll
    for (int t = 0; t < 8; ++t) {
        float px = (float)gx + OU[t] * s;
        float py = (float)gy + OV[t] * s;
        float x0f = floorf(px), y0f = floorf(py);
        float fx = px - x0f, fy = py - y0f;
        int x0 = clampi((int)x0f, 0, Wd - 1);
        int x1 = min(x0 + 1, Wd - 1);
        int y0 = clampi((int)y0f, 0, Hd - 1);
        int y1 = min(y0 + 1, Hd - 1);
        float w00 = (1.f - fx) * (1.f - fy);
        float w01 = fx * (1.f - fy);
        float w10 = (1.f - fx) * fy;
        float w11 = fx * fy;
        #pragma unroll
        for (int c = 0; c < 3; ++c) {
            const float* p = xb + (size_t)c * HW;
            float bil = w00 * __ldg(&p[y0 * Wd + x0]) + w01 * __ldg(&p[y0 * Wd + x1])
                      + w10 * __ldg(&p[y1 * Wd + x0]) + w11 * __ldg(&p[y1 * Wd + x1]);
            su[c] += KU[t] * bil;
            sv[c] += KV[t] * bil;
        }
    }
    A = 0.f; Bv = 0.f; Cv = 0.f;
    #pragma unroll
    for (int c = 0; c < 3; ++c) {
        float l = (c == 0) ? 100.f : 1.f;
        float a = su[c] * l, b = sv[c] * l;
        A += a * a; Bv += b * b; Cv += a * b;
    }
}

// Vertical 5-tap stencil at (gy, col..col+3): vs = Sy*X, vg = Gy*X.
template<int JP>
__device__ __forceinline__ void vert(const float* __restrict__ plane, int gy, int col,
                                     float wm0, float wm1, float wp0, float wp1,
                                     float4& vs, float4& vg) {
    const int ym0 = max(gy - JP - 1, 0);
    const int ym1 = max(gy - JP, 0);
    const int yp0 = min(gy + JP, Hd - 1);
    const int yp1 = min(gy + JP + 1, Hd - 1);
    float4 m0 = __ldg((const float4*)(plane + (size_t)ym0 * Wd + col));
    float4 m1 = __ldg((const float4*)(plane + (size_t)ym1 * Wd + col));
    float4 ce = __ldg((const float4*)(plane + (size_t)gy  * Wd + col));
    float4 p0 = __ldg((const float4*)(plane + (size_t)yp0 * Wd + col));
    float4 p1 = __ldg((const float4*)(plane + (size_t)yp1 * Wd + col));
    float mpx = wm0 * m0.x + wm1 * m1.x;
    float mpy = wm0 * m0.y + wm1 * m1.y;
    float mpz = wm0 * m0.z + wm1 * m1.z;
    float mpw = wm0 * m0.w + wm1 * m1.w;
    float ppx = wp0 * p0.x + wp1 * p1.x;
    float ppy = wp0 * p0.y + wp1 * p1.y;
    float ppz = wp0 * p0.z + wp1 * p1.z;
    float ppw = wp0 * p0.w + wp1 * p1.w;
    vs.x = ce.x + mpx + ppx;  vg.x = ppx - mpx;
    vs.y = ce.y + mpy + ppy;  vg.y = ppy - mpy;
    vs.z = ce.z + mpz + ppz;  vg.z = ppz - mpz;
    vs.w = ce.w + mpw + ppw;  vg.w = ppw - mpw;
}

__device__ __forceinline__ float4 shup(float4 v) {
    float4 r;
    r.x = __shfl_up_sync(FULLM, v.x, 1);
    r.y = __shfl_up_sync(FULLM, v.y, 1);
    r.z = __shfl_up_sync(FULLM, v.z, 1);
    r.w = __shfl_up_sync(FULLM, v.w, 1);
    return r;
}
__device__ __forceinline__ float4 shdn(float4 v) {
    float4 r;
    r.x = __shfl_down_sync(FULLM, v.x, 1);
    r.y = __shfl_down_sync(FULLM, v.y, 1);
    r.z = __shfl_down_sync(FULLM, v.z, 1);
    r.w = __shfl_down_sync(FULLM, v.w, 1);
    return r;
}

template<int JP>
__device__ __forceinline__ void run(const float* __restrict__ xb, float s,
                                    float* __restrict__ out,
                                    int b, int lane, int xl, int axl, int gy0) {
    const float fp  = s - (float)JP;
    const float wp0 = 0.5f * (1.f - fp);
    const float wp1 = 0.5f * fp;
    const float wm0 = wp1;
    const float wm1 = wp0;

    constexpr int dM = 3 - JP;   // window base = xl - 4
    constexpr int dP = 4 + JP;

    float* out0 = out + ((size_t)b * 3 + 0) * HW;
    float* out1 = out + ((size_t)b * 3 + 1) * HW;
    float* out2 = out + ((size_t)b * 3 + 2) * HW;

    const bool xint = (xl >= 4) && (xl <= Wd - 8);   // all 4 px interior in x

    #pragma unroll
    for (int j = 0; j < ROWS; ++j) {
        const int gy = gy0 + j;
        float aA[4] = {0.f,0.f,0.f,0.f};
        float aB[4] = {0.f,0.f,0.f,0.f};
        float aC[4] = {0.f,0.f,0.f,0.f};

        #pragma unroll
        for (int c = 0; c < 3; ++c) {
            const float l = (c == 0) ? 100.f : 1.f;
            const float* plane = xb + (size_t)c * HW;

            float4 vS, vG, aS, aG;
            vert<JP>(plane, gy, xl,  wm0, wm1, wp0, wp1, vS, vG);
            vert<JP>(plane, gy, axl, wm0, wm1, wp0, wp1, aS, aG);

            float4 lS = shup(vS), lG = shup(vG);
            float4 rS = shdn(vS), rG = shdn(vG);
            if (lane == 0)  { lS = aS; lG = aG; }
            if (lane == 31) { rS = aS; rG = aG; }

            float sw[12] = {lS.x,lS.y,lS.z,lS.w, vS.x,vS.y,vS.z,vS.w, rS.x,rS.y,rS.z,rS.w};
            float gw[12] = {lG.x,lG.y,lG.z,lG.w, vG.x,vG.y,vG.z,vG.w, rG.x,rG.y,rG.z,rG.w};

            #pragma unroll
            for (int i = 0; i < 4; ++i) {
                float su = wp0 * sw[i + dP] + wp1 * sw[i + dP + 1]
                         - wm0 * sw[i + dM] - wm1 * sw[i + dM + 1];
                float sv = gw[i + 4]
                         + wm0 * gw[i + dM] + wm1 * gw[i + dM + 1]
                         + wp0 * gw[i + dP] + wp1 * gw[i + dP + 1];
                float a  = l * su;
                float bq = l * sv;
                aA[i] += a * a;
                aB[i] += bq * bq;
                aC[i] += a * bq;
            }
        }

        const bool yint = (gy >= 3) && (gy <= Hd - 4);
        const size_t o = (size_t)gy * Wd + xl;
        if (xint && yint) {
            *(float4*)(out0 + o) = make_float4(aA[0], aA[1], aA[2], aA[3]);
            *(float4*)(out1 + o) = make_float4(aB[0], aB[1], aB[2], aB[3]);
            *(float4*)(out2 + o) = make_float4(aC[0], aC[1], aC[2], aC[3]);
        } else {
            #pragma unroll
            for (int i = 0; i < 4; ++i) {
                int gx = xl + i;
                float A = aA[i], Bv = aB[i], Cv = aC[i];
                if (!(yint && gx >= 3 && gx <= Wd - 4)) {
                    exact_pixel(xb, s, gx, gy, A, Bv, Cv);
                }
                out0[o + i] = A;
                out1[o + i] = Bv;
                out2[o + i] = Cv;
            }
        }
    }
}

__global__ __launch_bounds__(NTH)
void st6_kernel(const float* __restrict__ x, const float* __restrict__ sigma,
                float* __restrict__ out) {
    const int tid  = threadIdx.x;
    const int lane = tid & 31;
    const int warp = tid >> 5;

    const int strip = blockIdx.x;                    // 0..7 (128-px column strips)
    const int b     = blockIdx.z;
    const int gy0   = (blockIdx.y * NW + warp) * ROWS;

    const int xbase = strip * 128;
    const int xl    = xbase + lane * 4;              // own float4 column
    int axl = (lane == 31) ? (xbase + 128) : (xbase - 4);
    axl = clampi(axl, 0, Wd - 4);                    // aux (halo) column

    const float s = __ldg(&sigma[b]);
    const int jp = clampi((int)floorf(s), 0, 2);
    const float* xb = x + (size_t)b * 3 * HW;

    if (jp == 0)      run<0>(xb, s, out, b, lane, xl, axl, gy0);
    else if (jp == 1) run<1>(xb, s, out, b, lane, xl, axl, gy0);
    else              run<2>(xb, s, out, b, lane, xl, axl, gy0);
}

extern "C" void kernel_launch(void* const* d_in, const int* in_sizes, int n_in,
                              void* d_out, int out_size) {
    const float* x     = (const float*)d_in[0];
    const float* sigma = (const float*)d_in[1];
    float* out = (float*)d_out;
    int B = in_sizes[1];

    dim3 grid(Wd / 128, Hd / (NW * ROWS), B);        // (8, 64, 4) = 2048 blocks
    st6_kernel<<<grid, NTH>>>(x, sigma, out);
}